// round 16
// baseline (speedup 1.0000x reference)
#include <cuda_runtime.h>
#include <cuda_fp16.h>
#include <cstdint>

#define NV 8192
#define NC 128

// -------------------- device scratch (no allocs allowed) --------------------
__device__ __half g_Eh[(size_t)NV * NV];   // E fp16 (written by GEMM1, read by GEMM2)
__device__ __half g_x[NV * NC];            // xw fp16
__device__ __half g_y[NV * NC];            // y  fp16
__device__ float g_part[2][NV * NC];       // split-K partials
__device__ float g_E0[64 * NC];
__device__ float g_E1[128 * NC];

// -------------------- helpers -------------------------------------------------
__device__ __forceinline__ uint32_t pack_h2(__half a, __half b) {
    __half2 p{a, b};
    return *(uint32_t*)&p;
}

// prep: xw fp16 + coef tables in one launch
__global__ void __launch_bounds__(256) prep_kernel(const float4* __restrict__ x4,
                                                   const float* __restrict__ mass,
                                                   uint2* __restrict__ xq,
                                                   const float* __restrict__ ev0,
                                                   const float* __restrict__ ev1,
                                                   const float* __restrict__ dt) {
    int b = blockIdx.x;
    if (b < 1024) {
        int idx = b * 256 + threadIdx.x;
        float m = mass[(idx * 4) >> 7];
        float4 v = x4[idx];
        xq[idx] = make_uint2(pack_h2(__float2half(v.x * m), __float2half(v.y * m)),
                             pack_h2(__float2half(v.z * m), __float2half(v.w * m)));
    } else {
        int t = (b - 1024) * 256 + threadIdx.x;   // 96 blocks cover 8192 + 16384
        if (t < 64 * NC) {
            int i = t >> 7, c = t & 127;
            g_E0[t] = __expf(-ev0[i] * dt[c]);
        } else {
            int t2 = t - 64 * NC;
            int j = t2 >> 7, c = t2 & 127;
            g_E1[t2] = __expf(-ev1[j] * dt[NC + c]);
        }
    }
}

// reduce GEMM1 split-K partials, apply coef, emit fp16 y [V][C]
__global__ void __launch_bounds__(256) reduce1_kernel(const float4* __restrict__ P0,
                                                      const float4* __restrict__ P1,
                                                      uint2* __restrict__ y,
                                                      const float4* __restrict__ E0,
                                                      const float4* __restrict__ E1) {
    int idx = blockIdx.x * 256 + threadIdx.x;       // over NV*NC/4
    int gm = (idx * 4) >> 7;
    int gn4 = idx & 31;
    float4 a = P0[idx], b = P1[idx];
    float4 c0 = E0[(gm >> 7) * 32 + gn4];
    float4 c1 = E1[(gm & 127) * 32 + gn4];
    float v0 = (a.x + b.x) * c0.x * c1.x;
    float v1 = (a.y + b.y) * c0.y * c1.y;
    float v2 = (a.z + b.z) * c0.z * c1.z;
    float v3 = (a.w + b.w) * c0.w * c1.w;
    y[idx] = make_uint2(pack_h2(__float2half(v0), __float2half(v1)),
                        pack_h2(__float2half(v2), __float2half(v3)));
}

__global__ void __launch_bounds__(256) reduce2_kernel(const float4* __restrict__ P0,
                                                      const float4* __restrict__ P1,
                                                      float4* __restrict__ out) {
    int idx = blockIdx.x * 256 + threadIdx.x;
    float4 a = P0[idx], b = P1[idx];
    out[idx] = make_float4(a.x + b.x, a.y + b.y, a.z + b.z, a.w + b.w);
}

// -------------------- mma.sync helpers ----------------------------------------
__device__ __forceinline__ void ldsm4(uint32_t* r, uint32_t addr) {
    asm volatile("ldmatrix.sync.aligned.m8n8.x4.shared.b16 {%0,%1,%2,%3}, [%4];"
                 : "=r"(r[0]), "=r"(r[1]), "=r"(r[2]), "=r"(r[3]) : "r"(addr));
}
__device__ __forceinline__ void ldsm4t(uint32_t* r, uint32_t addr) {
    asm volatile("ldmatrix.sync.aligned.m8n8.x4.trans.shared.b16 {%0,%1,%2,%3}, [%4];"
                 : "=r"(r[0]), "=r"(r[1]), "=r"(r[2]), "=r"(r[3]) : "r"(addr));
}
__device__ __forceinline__ void mma16816(float* d, const uint32_t* a, const uint32_t* b) {
    asm volatile("mma.sync.aligned.m16n8k16.row.col.f32.f16.f16.f32 "
                 "{%0,%1,%2,%3}, {%4,%5,%6,%7}, {%8,%9}, {%0,%1,%2,%3};"
                 : "+f"(d[0]), "+f"(d[1]), "+f"(d[2]), "+f"(d[3])
                 : "r"(a[0]), "r"(a[1]), "r"(a[2]), "r"(a[3]),
                   "r"(b[0]), "r"(b[1]));
}
#define CP16(dst, src) \
    asm volatile("cp.async.cg.shared.global [%0], [%1], 16;" :: "r"(dst), "l"(src) : "memory")

// -------------------- shared GEMM constants -------------------------------------
#define BM 64
#define BK 64
#define APAD 72                        // fp16 A pitch (144 B)
#define BPAD 136                       // fp16 B pitch (272 B)
#define A16_BYTES (BK * APAD * 2)      // 9216
#define B_BYTES   (BK * BPAD * 2)      // 17408

// ============ GEMM1 (fused E fp32->fp16): P = E^T @ xw, split-K ==================
// A arrives as fp32 via cp.async (3-stage); per ktile a vectorized smem pass
// converts to a single fp16 buffer (ldmatrix source) and STGs the stripe to g_Eh.
#define A32PITCH 272                   // bytes per fp32 A row (64*4 + 16 pad)
#define A32_BYTES (BK * A32PITCH)      // 17408
#define G1_STAGE (A32_BYTES + B_BYTES) // 34816
#define G1_SMEM  (3 * G1_STAGE + A16_BYTES)   // 113664 -> 2 CTAs/SM

__global__ void __launch_bounds__(256, 2)
gemm1_kernel(const float* __restrict__ E, const __half* __restrict__ Bx,
             __half* __restrict__ EhOut, float* __restrict__ P)
{
    extern __shared__ char smraw[];
    const uint32_t smbase = (uint32_t)__cvta_generic_to_shared(smraw);
    const uint32_t A16sm = smbase + 3 * G1_STAGE;
    const int tid  = threadIdx.x;
    const int lane = tid & 31, wid = tid >> 5;
    const int wm   = wid >> 2, wn = wid & 3;     // 2 x 4 warps (32x32 tiles)
    const int m0   = blockIdx.x * BM;
    const int kbase = blockIdx.y * (NV / 2);
    float* Pout = P + (size_t)blockIdx.y * NV * NC;

    auto issue = [&](int kt, int s) {
        const int k0 = kbase + kt * BK;
        const uint32_t sb = smbase + s * G1_STAGE;
        // A fp32: 64 rows x 16 chunks of 16B = 1024 -> 4/thread
#pragma unroll
        for (int i = 0; i < 4; i++) {
            int idx = i * 256 + tid;
            int r = idx >> 4, q = idx & 15;
            size_t ga = (size_t)(k0 + r) * NV + m0 + q * 4;
            CP16(sb + (uint32_t)(r * A32PITCH + q * 16), (const void*)(E + ga));
        }
        // B fp16: 64 rows x 16 chunks
#pragma unroll
        for (int i = 0; i < 4; i++) {
            int idx = i * 256 + tid;
            int r = idx >> 4, q = idx & 15;
            size_t gb = (size_t)(k0 + r) * NC + q * 8;
            CP16(sb + A32_BYTES + (uint32_t)(r * BPAD + q * 8) * 2, (const void*)(Bx + gb));
        }
        asm volatile("cp.async.commit_group;" ::: "memory");
    };

    // conversion assignment: thread -> A row r (k-dim), 16 consecutive m floats
    const int cr = tid >> 2;
    const int cq = (tid & 3) * 16;

    auto convertA = [&](int kt, int s) {
        const char* src = smraw + s * G1_STAGE + cr * A32PITCH + cq * 4;
        float4 f0 = *(const float4*)(src);
        float4 f1 = *(const float4*)(src + 16);
        float4 f2 = *(const float4*)(src + 32);
        float4 f3 = *(const float4*)(src + 48);
        uint32_t h[8];
        __half2 p;
        p = __floats2half2_rn(f0.x, f0.y); h[0] = *(uint32_t*)&p;
        p = __floats2half2_rn(f0.z, f0.w); h[1] = *(uint32_t*)&p;
        p = __floats2half2_rn(f1.x, f1.y); h[2] = *(uint32_t*)&p;
        p = __floats2half2_rn(f1.z, f1.w); h[3] = *(uint32_t*)&p;
        p = __floats2half2_rn(f2.x, f2.y); h[4] = *(uint32_t*)&p;
        p = __floats2half2_rn(f2.z, f2.w); h[5] = *(uint32_t*)&p;
        p = __floats2half2_rn(f3.x, f3.y); h[6] = *(uint32_t*)&p;
        p = __floats2half2_rn(f3.z, f3.w); h[7] = *(uint32_t*)&p;
        uint4 lo = make_uint4(h[0], h[1], h[2], h[3]);
        uint4 hi = make_uint4(h[4], h[5], h[6], h[7]);
        char* dst = smraw + 3 * G1_STAGE + (cr * APAD + cq) * 2;
        *(uint4*)(dst)      = lo;
        *(uint4*)(dst + 16) = hi;
        uint4* gd = (uint4*)(EhOut + (size_t)(kbase + kt * BK + cr) * NV + m0 + cq);
        gd[0] = lo; gd[1] = hi;
    };

    float acc[2][4][4];
#pragma unroll
    for (int a = 0; a < 2; a++)
#pragma unroll
        for (int b = 0; b < 4; b++)
#pragma unroll
            for (int q = 0; q < 4; q++) acc[a][b][q] = 0.0f;

    auto compute = [&](int s) {
        const uint32_t Bb = smbase + s * G1_STAGE + A32_BYTES;
#pragma unroll
        for (int ks = 0; ks < 4; ks++) {
            uint32_t af[2][4], bf[2][4];
#pragma unroll
            for (int mi = 0; mi < 2; mi++) {
                int krow = ks * 16 + (lane & 7) + ((lane >> 4) << 3);
                int mcol = wm * 32 + mi * 16 + (lane & 8);
                ldsm4t(af[mi], A16sm + (uint32_t)(krow * APAD + mcol) * 2);
            }
#pragma unroll
            for (int nj2 = 0; nj2 < 2; nj2++) {
                int krow = ks * 16 + (lane & 15);
                int ncol = wn * 32 + nj2 * 16 + ((lane >> 4) << 3);
                ldsm4t(bf[nj2], Bb + (uint32_t)(krow * BPAD + ncol) * 2);
            }
#pragma unroll
            for (int mi = 0; mi < 2; mi++)
#pragma unroll
                for (int nj = 0; nj < 4; nj++)
                    mma16816(acc[mi][nj], af[mi], &bf[nj >> 1][(nj & 1) * 2]);
        }
    };

    const int NIT = (NV / 2) / BK;   // 64
    issue(0, 0);
    issue(1, 1);
#pragma unroll 1
    for (int kt = 0; kt < NIT; kt++) {
        const int s = kt % 3;
        if (kt < NIT - 1) asm volatile("cp.async.wait_group 1;" ::: "memory");
        else              asm volatile("cp.async.wait_group 0;" ::: "memory");
        __syncthreads();                 // stage kt ready; A16 free (prev compute done)
        convertA(kt, s);                 // A32[s] -> A16 (+ STG to g_Eh)
        if (kt + 2 < NIT) issue(kt + 2, (kt + 2) % 3);
        __syncthreads();                 // A16 visible to all warps
        compute(s);
    }

    // epilogue: fp32 partials
#pragma unroll
    for (int mi = 0; mi < 2; mi++)
#pragma unroll
        for (int q = 0; q < 2; q++) {
            int gm = m0 + wm * 32 + mi * 16 + (lane >> 2) + q * 8;
#pragma unroll
            for (int nj = 0; nj < 4; nj++) {
                int gn = wn * 32 + nj * 8 + (lane & 3) * 2;
                *(float2*)&Pout[(size_t)gm * NC + gn] =
                    make_float2(acc[mi][nj][q * 2 + 0], acc[mi][nj][q * 2 + 1]);
            }
        }
}

// ============ GEMM2: P = E @ y, split-K (R13 proven) =============================
#define G2_STAGE (A16_BYTES + B_BYTES)    // 26624
#define G2_SMEM  (3 * G2_STAGE)           // 79872 -> 2 CTAs/SM

__global__ void __launch_bounds__(256, 2)
gemm2_kernel(const __half* __restrict__ A, const __half* __restrict__ B,
             float* __restrict__ P)
{
    extern __shared__ __half sm[];
    const uint32_t smbase = (uint32_t)__cvta_generic_to_shared(sm);
    const int tid  = threadIdx.x;
    const int lane = tid & 31, wid = tid >> 5;
    const int wm   = wid >> 2, wn = wid & 3;
    const int m0   = blockIdx.x * BM;
    const int kbase = blockIdx.y * (NV / 2);
    float* Pout = P + (size_t)blockIdx.y * NV * NC;

    auto issue = [&](int kt, int s) {
        const int k0 = kbase + kt * BK;
        const uint32_t sb = smbase + s * G2_STAGE;
#pragma unroll
        for (int i = 0; i < 2; i++) {
            int idx = i * 256 + tid;
            int r = idx >> 3, q = idx & 7;
            size_t ga = (size_t)(m0 + r) * NV + k0 + q * 8;
            CP16(sb + (uint32_t)(r * APAD + q * 8) * 2, (const void*)(A + ga));
        }
#pragma unroll
        for (int i = 0; i < 4; i++) {
            int idx = i * 256 + tid;
            int r = idx >> 4, q = idx & 15;
            size_t gb = (size_t)(k0 + r) * NC + q * 8;
            CP16(sb + A16_BYTES + (uint32_t)(r * BPAD + q * 8) * 2, (const void*)(B + gb));
        }
        asm volatile("cp.async.commit_group;" ::: "memory");
    };

    float acc[2][4][4];
#pragma unroll
    for (int a = 0; a < 2; a++)
#pragma unroll
        for (int b = 0; b < 4; b++)
#pragma unroll
            for (int q = 0; q < 4; q++) acc[a][b][q] = 0.0f;

    auto compute = [&](int s) {
        const uint32_t Ab = smbase + s * G2_STAGE;
        const uint32_t Bb = Ab + A16_BYTES;
#pragma unroll
        for (int ks = 0; ks < 4; ks++) {
            uint32_t af[2][4], bf[2][4];
#pragma unroll
            for (int mi = 0; mi < 2; mi++) {
                int mrow = wm * 32 + mi * 16 + (lane & 15);
                int kcol = ks * 16 + ((lane >> 4) << 3);
                ldsm4(af[mi], Ab + (uint32_t)(mrow * APAD + kcol) * 2);
            }
#pragma unroll
            for (int nj2 = 0; nj2 < 2; nj2++) {
                int krow = ks * 16 + (lane & 15);
                int ncol = wn * 32 + nj2 * 16 + ((lane >> 4) << 3);
                ldsm4t(bf[nj2], Bb + (uint32_t)(krow * BPAD + ncol) * 2);
            }
#pragma unroll
            for (int mi = 0; mi < 2; mi++)
#pragma unroll
                for (int nj = 0; nj < 4; nj++)
                    mma16816(acc[mi][nj], af[mi], &bf[nj >> 1][(nj & 1) * 2]);
        }
    };

    const int NIT = (NV / 2) / BK;
    issue(0, 0);
    issue(1, 1);
#pragma unroll 1
    for (int kt = 0; kt < NIT; kt++) {
        if (kt < NIT - 1) asm volatile("cp.async.wait_group 1;" ::: "memory");
        else              asm volatile("cp.async.wait_group 0;" ::: "memory");
        __syncthreads();
        compute(kt % 3);
        if (kt + 2 < NIT) issue(kt + 2, (kt + 2) % 3);
    }

#pragma unroll
    for (int mi = 0; mi < 2; mi++)
#pragma unroll
        for (int q = 0; q < 2; q++) {
            int gm = m0 + wm * 32 + mi * 16 + (lane >> 2) + q * 8;
#pragma unroll
            for (int nj = 0; nj < 4; nj++) {
                int gn = wn * 32 + nj * 8 + (lane & 3) * 2;
                *(float2*)&Pout[(size_t)gm * NC + gn] =
                    make_float2(acc[mi][nj][q * 2 + 0], acc[mi][nj][q * 2 + 1]);
            }
        }
}

// -------------------- launch -----------------------------------------------------
// Inputs: 0:x[V,C] 1:edge_index 2:L 3:mass[V] 4:evals0[64] 5:evals1[128]
//         6:evecs[V,V] 7:diffusion_time[2,C]   Output: [V,C] fp32
extern "C" void kernel_launch(void* const* d_in, const int* in_sizes, int n_in,
                              void* d_out, int out_size) {
    const float* x      = (const float*)d_in[0];
    const float* mass   = (const float*)d_in[3];
    const float* evals0 = (const float*)d_in[4];
    const float* evals1 = (const float*)d_in[5];
    const float* evecs  = (const float*)d_in[6];
    const float* dt     = (const float*)d_in[7];
    float* out          = (float*)d_out;

    __half *Eh, *xq, *yq;
    float *P, *E0, *E1;
    cudaGetSymbolAddress((void**)&Eh, g_Eh);
    cudaGetSymbolAddress((void**)&xq, g_x);
    cudaGetSymbolAddress((void**)&yq, g_y);
    cudaGetSymbolAddress((void**)&P,  g_part);
    cudaGetSymbolAddress((void**)&E0, g_E0);
    cudaGetSymbolAddress((void**)&E1, g_E1);

    cudaFuncSetAttribute(gemm1_kernel, cudaFuncAttributeMaxDynamicSharedMemorySize, G1_SMEM);
    cudaFuncSetAttribute(gemm2_kernel, cudaFuncAttributeMaxDynamicSharedMemorySize, G2_SMEM);

    prep_kernel<<<1120, 256>>>((const float4*)x, mass, (uint2*)xq, evals0, evals1, dt);

    const int NQ = NV * NC / 4 / 256;
    // GEMM1: P = E^T @ xw (split-K); converts E fp32->fp16 inline and emits g_Eh
    gemm1_kernel<<<dim3(NV / BM, 2), 256, G1_SMEM>>>(evecs, xq, Eh, P);
    // y = coef .* (P0 + P1) -> fp16
    reduce1_kernel<<<NQ, 256>>>((const float4*)P, (const float4*)(P + NV * NC),
                                (uint2*)yq, (const float4*)E0, (const float4*)E1);
    // GEMM2: P = E @ y (split-K)
    gemm2_kernel<<<dim3(NV / BM, 2), 256, G2_SMEM>>>(Eh, yq, P);
    // out = P0 + P1
    reduce2_kernel<<<NQ, 256>>>((const float4*)P, (const float4*)(P + NV * NC), (float4*)out);
}

// round 17
// speedup vs baseline: 1.1326x; 1.1326x over previous
#include <cuda_runtime.h>
#include <cuda_fp16.h>
#include <cstdint>

#define NV 8192
#define NC 128
#define NSPLIT 4

// -------------------- device scratch (no allocs allowed) --------------------
__device__ __half g_Eh[(size_t)NV * NV];   // E fp16, row-major
__device__ __half g_x[NV * NC];            // xw fp16
__device__ __half g_y[NV * NC];            // y  fp16
__device__ float g_part[NSPLIT][NV * NC];  // split-K partials
__device__ float g_E0[64 * NC];
__device__ float g_E1[128 * NC];

// -------------------- helpers -------------------------------------------------
__device__ __forceinline__ uint32_t pack_h2(__half a, __half b) {
    __half2 p{a, b};
    return *(uint32_t*)&p;
}

// prep: xw fp16 + coef tables in one launch
__global__ void __launch_bounds__(256) prep_kernel(const float4* __restrict__ x4,
                                                   const float* __restrict__ mass,
                                                   uint2* __restrict__ xq,
                                                   const float* __restrict__ ev0,
                                                   const float* __restrict__ ev1,
                                                   const float* __restrict__ dt) {
    int b = blockIdx.x;
    if (b < 1024) {
        int idx = b * 256 + threadIdx.x;
        float m = mass[(idx * 4) >> 7];
        float4 v = x4[idx];
        xq[idx] = make_uint2(pack_h2(__float2half(v.x * m), __float2half(v.y * m)),
                             pack_h2(__float2half(v.z * m), __float2half(v.w * m)));
    } else {
        int t = (b - 1024) * 256 + threadIdx.x;
        if (t < 64 * NC) {
            int i = t >> 7, c = t & 127;
            g_E0[t] = __expf(-ev0[i] * dt[c]);
        } else {
            int t2 = t - 64 * NC;
            int j = t2 >> 7, c = t2 & 127;
            g_E1[t2] = __expf(-ev1[j] * dt[NC + c]);
        }
    }
}

// E fp32 -> fp16, 8 values per thread, 16B stores
__global__ void __launch_bounds__(256) convE_kernel(const float4* __restrict__ E4,
                                                    uint4* __restrict__ Eh) {
    const size_t N8 = (size_t)NV * NV / 8;
    for (size_t idx = (size_t)blockIdx.x * 256 + threadIdx.x; idx < N8;
         idx += (size_t)gridDim.x * 256) {
        float4 a = E4[idx * 2], b = E4[idx * 2 + 1];
        Eh[idx] = make_uint4(pack_h2(__float2half(a.x), __float2half(a.y)),
                             pack_h2(__float2half(a.z), __float2half(a.w)),
                             pack_h2(__float2half(b.x), __float2half(b.y)),
                             pack_h2(__float2half(b.z), __float2half(b.w)));
    }
}

// reduce 4 split-K partials, apply coef, emit fp16 y
__global__ void __launch_bounds__(256) reduce1_kernel(const float4* __restrict__ P,
                                                      uint2* __restrict__ y,
                                                      const float4* __restrict__ E0,
                                                      const float4* __restrict__ E1) {
    int idx = blockIdx.x * 256 + threadIdx.x;       // over NV*NC/4
    int gm = (idx * 4) >> 7;
    int gn4 = idx & 31;
    const int Q = NV * NC / 4;
    float4 a = P[idx], b = P[idx + Q], c = P[idx + 2 * Q], d = P[idx + 3 * Q];
    float4 c0 = E0[(gm >> 7) * 32 + gn4];
    float4 c1 = E1[(gm & 127) * 32 + gn4];
    float v0 = (a.x + b.x + c.x + d.x) * c0.x * c1.x;
    float v1 = (a.y + b.y + c.y + d.y) * c0.y * c1.y;
    float v2 = (a.z + b.z + c.z + d.z) * c0.z * c1.z;
    float v3 = (a.w + b.w + c.w + d.w) * c0.w * c1.w;
    y[idx] = make_uint2(pack_h2(__float2half(v0), __float2half(v1)),
                        pack_h2(__float2half(v2), __float2half(v3)));
}

__global__ void __launch_bounds__(256) reduce2_kernel(const float4* __restrict__ P,
                                                      float4* __restrict__ out) {
    int idx = blockIdx.x * 256 + threadIdx.x;
    const int Q = NV * NC / 4;
    float4 a = P[idx], b = P[idx + Q], c = P[idx + 2 * Q], d = P[idx + 3 * Q];
    out[idx] = make_float4(a.x + b.x + c.x + d.x, a.y + b.y + c.y + d.y,
                           a.z + b.z + c.z + d.z, a.w + b.w + c.w + d.w);
}

// -------------------- mma.sync helpers ----------------------------------------
__device__ __forceinline__ void ldsm4(uint32_t* r, uint32_t addr) {
    asm volatile("ldmatrix.sync.aligned.m8n8.x4.shared.b16 {%0,%1,%2,%3}, [%4];"
                 : "=r"(r[0]), "=r"(r[1]), "=r"(r[2]), "=r"(r[3]) : "r"(addr));
}
__device__ __forceinline__ void ldsm4t(uint32_t* r, uint32_t addr) {
    asm volatile("ldmatrix.sync.aligned.m8n8.x4.trans.shared.b16 {%0,%1,%2,%3}, [%4];"
                 : "=r"(r[0]), "=r"(r[1]), "=r"(r[2]), "=r"(r[3]) : "r"(addr));
}
__device__ __forceinline__ void mma16816(float* d, const uint32_t* a, const uint32_t* b) {
    asm volatile("mma.sync.aligned.m16n8k16.row.col.f32.f16.f16.f32 "
                 "{%0,%1,%2,%3}, {%4,%5,%6,%7}, {%8,%9}, {%0,%1,%2,%3};"
                 : "+f"(d[0]), "+f"(d[1]), "+f"(d[2]), "+f"(d[3])
                 : "r"(a[0]), "r"(a[1]), "r"(a[2]), "r"(a[3]),
                   "r"(b[0]), "r"(b[1]));
}
#define CP16(dst, src) \
    asm volatile("cp.async.cg.shared.global [%0], [%1], 16;" :: "r"(dst), "l"(src) : "memory")

// -------------------- GEMM config ----------------------------------------------
// BM=128, BN=128, BK=64. Warps 4(M) x 2(N); warp tile 32x64. Split-K=4.
#define BM 128
#define BK 64
#define BPAD 136
#define B_BYTES (BK * BPAD * 2)            // 17408

template <int TRANS_A>
struct Cfg {
    static constexpr int A_ROWS  = TRANS_A ? 64 : 128;
    static constexpr int A_PAD   = TRANS_A ? 136 : 72;       // halves
    static constexpr int A_BYTES = A_ROWS * A_PAD * 2;       // 17408 / 18432
    static constexpr int STAGE   = A_BYTES + B_BYTES;        // 34816 / 35840
    static constexpr int SMEM    = 3 * STAGE;                // 104448 / 107520
};

// Split-K GEMM partial: blockIdx.x = M tile (64), blockIdx.y = K quarter (4).
template <int TRANS_A>
__global__ void __launch_bounds__(256, 2)
gemm_kernel(const __half* __restrict__ A, const __half* __restrict__ B,
            float* __restrict__ P)
{
    using CF = Cfg<TRANS_A>;
    extern __shared__ __half sm[];
    const uint32_t smbase = (uint32_t)__cvta_generic_to_shared(sm);
    const int tid  = threadIdx.x;
    const int lane = tid & 31, wid = tid >> 5;
    const int wm   = wid >> 1, wn = wid & 1;       // 4 x 2 warps, warp tile 32x64
    const int m0   = blockIdx.x * BM;
    const int kbase = blockIdx.y * (NV / NSPLIT);
    float* Pout = P + (size_t)blockIdx.y * NV * NC;

    auto issue = [&](int kt, int s) {
        const int k0 = kbase + kt * BK;
        const uint32_t sb = smbase + s * CF::STAGE;
#pragma unroll
        for (int i = 0; i < 4; i++) {              // A: 1024 chunks of 16B
            int idx = i * 256 + tid;
            int r, q;
            size_t ga;
            uint32_t so;
            if (TRANS_A) {
                r = idx >> 4; q = idx & 15;        // [64 k][128 m]
                ga = (size_t)(k0 + r) * NV + m0 + q * 8;
                so = (uint32_t)(r * CF::A_PAD + q * 8) * 2;
            } else {
                r = idx >> 3; q = idx & 7;         // [128 m][64 k]
                ga = (size_t)(m0 + r) * NV + k0 + q * 8;
                so = (uint32_t)(r * CF::A_PAD + q * 8) * 2;
            }
            CP16(sb + so, (const void*)(A + ga));
        }
#pragma unroll
        for (int i = 0; i < 4; i++) {              // B: 1024 chunks
            int idx = i * 256 + tid;
            int r = idx >> 4, q = idx & 15;
            size_t gb = (size_t)(k0 + r) * NC + q * 8;
            CP16(sb + CF::A_BYTES + (uint32_t)(r * BPAD + q * 8) * 2, (const void*)(B + gb));
        }
        asm volatile("cp.async.commit_group;" ::: "memory");
    };

    float acc[2][8][4];
#pragma unroll
    for (int a = 0; a < 2; a++)
#pragma unroll
        for (int b = 0; b < 8; b++)
#pragma unroll
            for (int q = 0; q < 4; q++) acc[a][b][q] = 0.0f;

    auto compute = [&](int s) {
        const uint32_t Ab = smbase + s * CF::STAGE;
        const uint32_t Bb = Ab + CF::A_BYTES;
#pragma unroll
        for (int ks = 0; ks < 4; ks++) {
            uint32_t af[2][4], bf[4][4];
#pragma unroll
            for (int mi = 0; mi < 2; mi++) {
                if (TRANS_A) {
                    int krow = ks * 16 + (lane & 7) + ((lane >> 4) << 3);
                    int mcol = wm * 32 + mi * 16 + (lane & 8);
                    ldsm4t(af[mi], Ab + (uint32_t)(krow * CF::A_PAD + mcol) * 2);
                } else {
                    int mrow = wm * 32 + mi * 16 + (lane & 15);
                    int kcol = ks * 16 + ((lane >> 4) << 3);
                    ldsm4(af[mi], Ab + (uint32_t)(mrow * CF::A_PAD + kcol) * 2);
                }
            }
#pragma unroll
            for (int nj2 = 0; nj2 < 4; nj2++) {
                int krow = ks * 16 + (lane & 15);
                int ncol = wn * 64 + nj2 * 16 + ((lane >> 4) << 3);
                ldsm4t(bf[nj2], Bb + (uint32_t)(krow * BPAD + ncol) * 2);
            }
#pragma unroll
            for (int mi = 0; mi < 2; mi++)
#pragma unroll
                for (int nj = 0; nj < 8; nj++)
                    mma16816(acc[mi][nj], af[mi], &bf[nj >> 1][(nj & 1) * 2]);
        }
    };

    const int NIT = (NV / NSPLIT) / BK;   // 32
    issue(0, 0);
    issue(1, 1);
#pragma unroll 1
    for (int kt = 0; kt < NIT; kt++) {
        if (kt < NIT - 1) asm volatile("cp.async.wait_group 1;" ::: "memory");
        else              asm volatile("cp.async.wait_group 0;" ::: "memory");
        __syncthreads();
        compute(kt % 3);
        if (kt + 2 < NIT) issue(kt + 2, (kt + 2) % 3);
    }

    // ---- epilogue: fp32 partials ----
#pragma unroll
    for (int mi = 0; mi < 2; mi++)
#pragma unroll
        for (int q = 0; q < 2; q++) {
            int gm = m0 + wm * 32 + mi * 16 + (lane >> 2) + q * 8;
#pragma unroll
            for (int nj = 0; nj < 8; nj++) {
                int gn = wn * 64 + nj * 8 + (lane & 3) * 2;
                *(float2*)&Pout[(size_t)gm * NC + gn] =
                    make_float2(acc[mi][nj][q * 2 + 0], acc[mi][nj][q * 2 + 1]);
            }
        }
}

// -------------------- launch -----------------------------------------------------
// Inputs: 0:x[V,C] 1:edge_index 2:L 3:mass[V] 4:evals0[64] 5:evals1[128]
//         6:evecs[V,V] 7:diffusion_time[2,C]   Output: [V,C] fp32
extern "C" void kernel_launch(void* const* d_in, const int* in_sizes, int n_in,
                              void* d_out, int out_size) {
    const float* x      = (const float*)d_in[0];
    const float* mass   = (const float*)d_in[3];
    const float* evals0 = (const float*)d_in[4];
    const float* evals1 = (const float*)d_in[5];
    const float* evecs  = (const float*)d_in[6];
    const float* dt     = (const float*)d_in[7];
    float* out          = (float*)d_out;

    __half *Eh, *xq, *yq;
    float *P, *E0, *E1;
    cudaGetSymbolAddress((void**)&Eh, g_Eh);
    cudaGetSymbolAddress((void**)&xq, g_x);
    cudaGetSymbolAddress((void**)&yq, g_y);
    cudaGetSymbolAddress((void**)&P,  g_part);
    cudaGetSymbolAddress((void**)&E0, g_E0);
    cudaGetSymbolAddress((void**)&E1, g_E1);

    cudaFuncSetAttribute(gemm_kernel<1>, cudaFuncAttributeMaxDynamicSharedMemorySize, Cfg<1>::SMEM);
    cudaFuncSetAttribute(gemm_kernel<0>, cudaFuncAttributeMaxDynamicSharedMemorySize, Cfg<0>::SMEM);

    prep_kernel<<<1120, 256>>>((const float4*)x, mass, (uint2*)xq, evals0, evals1, dt);
    convE_kernel<<<2368, 256>>>((const float4*)evecs, (uint4*)Eh);

    const int NQ = NV * NC / 4 / 256;
    // GEMM1 partials: P = E^T @ xw  (split-K=4)
    gemm_kernel<1><<<dim3(NV / BM, NSPLIT), 256, Cfg<1>::SMEM>>>(Eh, xq, P);
    // y = coef .* sum(P)
    reduce1_kernel<<<NQ, 256>>>((const float4*)P, (uint2*)yq,
                                (const float4*)E0, (const float4*)E1);
    // GEMM2 partials: P = E @ y  (split-K=4)
    gemm_kernel<0><<<dim3(NV / BM, NSPLIT), 256, Cfg<0>::SMEM>>>(Eh, yq, P);
    // out = sum(P)
    reduce2_kernel<<<NQ, 256>>>((const float4*)P, (float4*)out);
}